// round 16
// baseline (speedup 1.0000x reference)
#include <cuda_runtime.h>
#include <cuda_bf16.h>
#include <cstdint>

// ---------------------------------------------------------------------------
// Problem constants
// ---------------------------------------------------------------------------
#define DX      16
#define DY      8
#define MR      64
#define MBAR    256
#define NT      9
#define GOUT    64
#define HX      1024
#define EX_DIM  512
#define HRNN    512
#define HB      2048
#define TOTAL   2049
#define M_TOTAL 16640           // (MR+1)*MBAR
#define MTILES  130             // M_TOTAL / 128

// ---------------------------------------------------------------------------
// Scratch (__device__ globals; referenced ONLY from device code)
// ---------------------------------------------------------------------------
__device__ __nv_bfloat16 g_EXh[(size_t)M_TOTAL * EX_DIM];
__device__ __nv_bfloat16 g_EXl[(size_t)M_TOTAL * EX_DIM];
__device__ __nv_bfloat16 g_W2Th[EX_DIM * HX],  g_W2Tl[EX_DIM * HX];   // [n][k]
__device__ __nv_bfloat16 g_W3Th[HB * EX_DIM],  g_W3Tl[HB * EX_DIM];   // [n][k]
__device__ float g_h0[HRNN], g_h1buf[HRNN];
__device__ float g_bb1eff[HB];
__device__ float g_Tb[MBAR * HX];        // tanh(basepre) (bx1 folded in)
__device__ float g_Td[MR * HX];          // tanh(delta_j)
__device__ float g_coeff[M_TOTAL];       // signed reduction weights per row
__device__ float g_Vpart[(size_t)MTILES * HB];
__device__ float g_sipart[8 * GOUT];
__device__ int   g_sync[16];             // rnn cross-CTA step barrier counters

__device__ __forceinline__ int read_int(const int* p) {
    int v = *p;
    if (v >= 0 && v < (1 << 20)) return v;
    return (int)__int_as_float(v);
}

// Fast tanh: 1 - 2/(e^{2x}+1). ~1e-6 abs err.
__device__ __forceinline__ float fast_tanh(float x) {
    float e = __expf(2.f * x);
    return 1.f - __fdividef(2.f, e + 1.f);
}

// ---------------------------------------------------------------------------
// PTX helpers
// ---------------------------------------------------------------------------
__device__ __forceinline__ uint32_t smem_u32(const void* p) {
    uint32_t a;
    asm("{ .reg .u64 t; cvta.to.shared.u64 t, %1; cvt.u32.u64 %0, t; }"
        : "=r"(a) : "l"(p));
    return a;
}
__device__ __forceinline__ void cp16(uint32_t dst, const void* src) {
    asm volatile("cp.async.cg.shared.global [%0], [%1], 16;"
                 :: "r"(dst), "l"(src) : "memory");
}
#define CP_COMMIT() asm volatile("cp.async.commit_group;" ::: "memory")
#define CP_WAIT(n)  asm volatile("cp.async.wait_group %0;" :: "n"(n) : "memory")

#define STS128(addr, w0, w1, w2, w3)                                           \
    asm volatile("st.shared.v4.b32 [%0], {%1,%2,%3,%4};"                       \
                 :: "r"(addr), "r"(w0), "r"(w1), "r"(w2), "r"(w3) : "memory")

#define LDSM4(r0, r1, r2, r3, addr)                                            \
    asm volatile("ldmatrix.sync.aligned.m8n8.x4.shared.b16 {%0,%1,%2,%3}, [%4];" \
                 : "=r"(r0), "=r"(r1), "=r"(r2), "=r"(r3) : "r"(addr))

#define MMA16816(d, a, b)                                                      \
    asm volatile("mma.sync.aligned.m16n8k16.row.col.f32.bf16.bf16.f32 "        \
                 "{%0,%1,%2,%3}, {%4,%5,%6,%7}, {%8,%9}, {%0,%1,%2,%3};"       \
                 : "+f"((d)[0]), "+f"((d)[1]), "+f"((d)[2]), "+f"((d)[3])      \
                 : "r"((a)[0]), "r"((a)[1]), "r"((a)[2]), "r"((a)[3]),         \
                   "r"((b)[0]), "r"((b)[1]))

__device__ __forceinline__ uint32_t pack_bf16(float a, float b) {
    __nv_bfloat162 t = __halves2bfloat162(__float2bfloat16(a), __float2bfloat16(b));
    return *(uint32_t*)&t;
}

// ---------------------------------------------------------------------------
// Weight prep (two launches to keep gemm2 at ncu launch index 3).
// which==0: Wx2 -> W2T (512 blocks) + zero g_sync.
// which==1: Wb1[1:513] -> W3T (1024 blocks).
// ---------------------------------------------------------------------------
__global__ void prep_w(const float* __restrict__ src, int which) {
    if (which == 0 && blockIdx.x == 0 && threadIdx.y == 0 && threadIdx.x < 16)
        g_sync[threadIdx.x] = 0;
    int b = blockIdx.x;
    int srcStride, rowOff, Kdim, kt, nt;
    __nv_bfloat16 *dh, *dl;
    if (which == 0) {
        srcStride = EX_DIM; rowOff = 0; Kdim = HX;
        dh = g_W2Th; dl = g_W2Tl; kt = b & 31; nt = b >> 5;
    } else {
        srcStride = HB; rowOff = 1; Kdim = EX_DIM;
        dh = g_W3Th; dl = g_W3Tl; kt = b & 15; nt = b >> 4;
    }
    int kb = kt * 32, nb = nt * 32;
    __shared__ float t[32][33];
    int tx = threadIdx.x, ty = threadIdx.y;
#pragma unroll
    for (int dy = 0; dy < 32; dy += 8)
        t[ty + dy][tx] = src[(size_t)(rowOff + kb + ty + dy) * srcStride + nb + tx];
    __syncthreads();
#pragma unroll
    for (int dy = 0; dy < 32; dy += 8) {
        int n = nb + ty + dy, k = kb + tx;
        float v = t[tx][ty + dy];
        __nv_bfloat16 h = __float2bfloat16(v);
        dh[(size_t)n * Kdim + k] = h;
        dl[(size_t)n * Kdim + k] = __float2bfloat16(v - __bfloat162float(h));
    }
}

// bb1_eff[n] = bb1[n] + sum_h eY[h] * Wb1[513+h][n]
__global__ void bb1eff_kernel(const float* __restrict__ Wb1,
                              const float* __restrict__ bb1) {
    int n = blockIdx.x * 256 + threadIdx.x;
    float acc = bb1[n];
    const float* w = Wb1 + (size_t)(1 + EX_DIM) * HB + n;
#pragma unroll 8
    for (int h = 0; h < HRNN; h++) acc += g_h0[h] * w[(size_t)h * HB];
    g_bb1eff[n] = acc;
}

// ---------------------------------------------------------------------------
// Pre-activations -> TANH: rows 0..255 -> Tb, rows 256..319 -> Td
// ---------------------------------------------------------------------------
__global__ void pre_h1_kernel(const float* __restrict__ X,
                              const float* __restrict__ stoich,
                              const float* __restrict__ Wx1,
                              const float* __restrict__ bx1,
                              const int* kpp, const int* qpp) {
    __shared__ float xv[DX];
    int row = blockIdx.x;        // 0..319
    int tid = threadIdx.x;
    int kp = read_int(kpp), qp = read_int(qpp);
    int base = kp * MBAR;
    if (tid < DX) {
        xv[tid] = (row < MBAR)
            ? X[((size_t)qp * TOTAL + base + row) * DX + tid]
            : stoich[tid * MR + (row - MBAR)];
    }
    __syncthreads();
#pragma unroll
    for (int ci = 0; ci < 4; ci++) {
        int col = ci * 256 + tid;
        float acc = (row < MBAR) ? bx1[col] : 0.f;
#pragma unroll
        for (int d = 0; d < DX; d++) acc = fmaf(xv[d], Wx1[d * HX + col], acc);
        float t = fast_tanh(acc);
        if (row < MBAR) g_Tb[row * HX + col] = t;
        else            g_Td[(row - MBAR) * HX + col] = t;
    }
}

// ---------------------------------------------------------------------------
// GEMM2 + piggybacked tails.  Grid (2, 135):
//   y in 0..3          -> 8 RNN CTAs (r = y*2+x): 8 threads cooperate per
//                          hidden unit (u = tid>>3, sub = tid&7), shfl-reduce;
//                          cross-CTA spin barrier via g_sync (zeroed in prep0;
//                          first CTAs dispatched -> co-resident).
//   (x,y) == (0,4)     -> coeff (disp + base) in one CTA, per-thread
//   (x,y) == (1,4)     -> idle
//   y >= 5             -> GEMM tile row (y-5); EX = H1 @ W2T + bx2 with
//                          H1 = (Tb+Td)/(1+Tb*Td) computed in-kernel.
// GEMM config: 512 threads, 16 warps (2x8), warp tile 64x32, CTA 128x256,
// BK=32, 3-stage pipeline, issues interleaved, single barrier per chunk.
// ---------------------------------------------------------------------------
#define G2_NCH   32
#define G2_AT    8192u
#define G2_BT    16384u
#define G2_TBOFF 49152u
#define G2_TBSTR 144
#define G2_STAGE 67584u
#define G2_TDOFF (3u * G2_STAGE)
#define G2_SMEM  (3 * 67584 + 4096 + 128)

__global__ void __launch_bounds__(512, 1) gemm2_kernel(
    const float* __restrict__ bias,
    const float* __restrict__ Y,   const float* __restrict__ Wih,
    const float* __restrict__ Whh, const float* __restrict__ bh,
    const int* kptr, const int* qptr,
    const float* __restrict__ X,   const float* __restrict__ R,
    const float* __restrict__ stoich,
    const int* kpp, const int* qpp)
{
    const int tid = threadIdx.x;

    // ---------------- piggybacked tails ----------------
    if (blockIdx.y < 5) {
        if (blockIdx.y < 4) {
            // RNN CTA r: hidden units [r*64, r*64+64), 8 threads per unit.
            int r = (int)(blockIdx.y * 2 + blockIdx.x);
            int k = read_int(kptr), q = read_int(qptr);
            int steps = NT - 1 - k;
            int u = tid >> 3, sub = tid & 7;
            int i = r * 64 + u;
            float h = 0.f;
            for (int s = 0; s < steps; s++) {
                float partial = 0.f;
                if (s > 0) {
                    const float* hprev = (s & 1) ? g_h1buf : g_h0;
                    const float4* h4 = (const float4*)(hprev + sub * 64);
                    const float* wcol = Whh + (size_t)(sub * 64) * HRNN + i;
#pragma unroll 4
                    for (int kk = 0; kk < 16; kk++) {
                        float4 hv = h4[kk];
                        partial = fmaf(hv.x, wcol[(4 * kk + 0) * HRNN], partial);
                        partial = fmaf(hv.y, wcol[(4 * kk + 1) * HRNN], partial);
                        partial = fmaf(hv.z, wcol[(4 * kk + 2) * HRNN], partial);
                        partial = fmaf(hv.w, wcol[(4 * kk + 3) * HRNN], partial);
                    }
                }
                partial += __shfl_xor_sync(0xFFFFFFFFu, partial, 1);
                partial += __shfl_xor_sync(0xFFFFFFFFu, partial, 2);
                partial += __shfl_xor_sync(0xFFFFFFFFu, partial, 4);
                if (sub == 0) {
                    const float* y = Y + ((size_t)q * NT + (k + 1 + s)) * DY;
                    float acc = bh[i] + partial;
#pragma unroll
                    for (int d = 0; d < DY; d++)
                        acc += y[d] * Wih[d * HRNN + i];
                    h = fast_tanh(acc);
                    float* out = (s & 1) ? g_h0 : g_h1buf;
                    out[i] = h;
                }
                __threadfence();
                __syncthreads();
                if (tid == 0) {
                    atomicAdd(&g_sync[s], 1);
                    while (((volatile int*)g_sync)[s] < 8)
                        asm volatile("nanosleep.u32 64;");
                }
                __syncthreads();
                __threadfence();
            }
            if (sub == 0) g_h0[i] = h;
        } else if (blockIdx.x == 0 && tid < 256) {
            // coeff: per-thread over m, loop over j; base row folded in.
            int m = tid;
            int kp = read_int(kpp), qp = read_int(qpp);
            int base = kp * MBAR;
            float xr[DX];
#pragma unroll
            for (int d = 0; d < DX; d++)
                xr[d] = X[((size_t)qp * TOTAL + base + m) * DX + d];
            const float* R0 = R + ((size_t)qp * TOTAL + base + m) * MR;
            float bsum = 0.f;
            for (int j = 0; j < MR; j++) {
                bool valid = true;
#pragma unroll
                for (int d = 0; d < DX; d++)
                    valid = valid && (xr[d] + stoich[d * MR + j] >= 0.f);
                float w = valid ? (R0[MR + j] - R0[j]) : 0.f;
                g_coeff[(j + 1) * MBAR + m] = w;
                bsum += w;
            }
            g_coeff[m] = -bsum;
        }
        return;
    }

    // ---------------- GEMM tile path ----------------
    extern __shared__ char dsm[];
    char* basep = (char*)(((uintptr_t)dsm + 127) & ~(uintptr_t)127);
    const uint32_t baseu = smem_u32(basep);

    const int ty = (int)blockIdx.y - 5;            // 0..129
    const int lane = tid & 31, wid = tid >> 5;
    const int warp_m = wid >> 3, warp_n = wid & 7;
    const size_t growBase = (size_t)ty * 128;
    const int nbase = blockIdx.x * 256;
    const int jb = ty >> 1;
    const float* bprow = g_Tb + (size_t)((ty & 1) * 128) * HX;
    const float* tdrow = (jb > 0) ? (g_Td + (size_t)(jb - 1) * HX) : nullptr;

    float acc[4][4][4];
#pragma unroll
    for (int i = 0; i < 4; i++)
#pragma unroll
        for (int j = 0; j < 4; j++)
#pragma unroll
            for (int v = 0; v < 4; v++) acc[i][j][v] = 0.f;

    uint32_t aoff[4];
    {
        int r16 = lane & 15, half = lane >> 4;
#pragma unroll
        for (int i = 0; i < 4; i++) {
            int row = warp_m * 64 + i * 16 + r16;
            int perm = half ^ (row & 3) ^ ((row >> 2) & 1);
            aoff[i] = row * 64 + (perm << 4);
        }
    }
    uint32_t boff[2];
    {
        int rn = (lane >> 4) * 8 + (lane & 7);
        int c  = (lane >> 3) & 1;
#pragma unroll
        for (int j = 0; j < 2; j++) {
            int row = warp_n * 32 + j * 16 + rn;
            int perm = c ^ (row & 3) ^ ((row >> 2) & 1);
            boff[j] = 2 * G2_AT + row * 64 + (perm << 4);
        }
    }

    const int cix = tid & 3;

    auto issue_group = [&](int tb_c, int b_c) {
        if (tb_c < G2_NCH) {
            uint32_t tdst = baseu + (uint32_t)(tb_c % 3) * G2_STAGE + G2_TBOFF;
            int k0 = tb_c * 32;
#pragma unroll
            for (int q = 0; q < 2; q++) {
                int idx = q * 512 + tid;
                int row = idx >> 3, ch = idx & 7;
                cp16(tdst + row * G2_TBSTR + ch * 16,
                     bprow + (size_t)row * HX + k0 + ch * 4);
            }
        }
        if (b_c < G2_NCH) {
            uint32_t tb2 = baseu + (uint32_t)(b_c % 3) * G2_STAGE;
            int k0 = b_c * 32;
#pragma unroll
            for (int it = 0; it < 2; it++) {
                int idx = it * 512 + tid;
                int r = idx >> 2, c2 = idx & 3;
                uint32_t perm = (uint32_t)(c2 ^ (r & 3) ^ ((r >> 2) & 1));
                uint32_t d = tb2 + 2 * G2_AT + r * 64 + (perm << 4);
                cp16(d, g_W2Th + (size_t)(nbase + r) * HX + k0 + c2 * 8);
                cp16(d + G2_BT, g_W2Tl + (size_t)(nbase + r) * HX + k0 + c2 * 8);
            }
        }
        CP_COMMIT();
    };

    auto convert = [&](int tc) {
        int s = tc % 3;
        int r = tid >> 2;   // 0..127
        float td[8];
        if (jb > 0) {
            const float* tdp = (const float*)(basep + G2_TDOFF) + tc * 32 + cix * 8;
            float4 t0 = *(const float4*)tdp;
            float4 t1 = *(const float4*)(tdp + 4);
            td[0] = t0.x; td[1] = t0.y; td[2] = t0.z; td[3] = t0.w;
            td[4] = t1.x; td[5] = t1.y; td[6] = t1.z; td[7] = t1.w;
        }
        const float* tbp = (const float*)(basep + (size_t)s * G2_STAGE + G2_TBOFF
                                          + (size_t)r * G2_TBSTR) + cix * 8;
        float4 b0 = *(const float4*)tbp;
        float4 b1 = *(const float4*)(tbp + 4);
        float tb[8] = {b0.x, b0.y, b0.z, b0.w, b1.x, b1.y, b1.z, b1.w};
        float h[8];
        if (jb > 0) {
#pragma unroll
            for (int e = 0; e < 8; e++)
                h[e] = __fdividef(tb[e] + td[e], fmaf(tb[e], td[e], 1.f));
        } else {
#pragma unroll
            for (int e = 0; e < 8; e++) h[e] = tb[e];
        }
        uint32_t hv[4], lv[4];
#pragma unroll
        for (int q = 0; q < 4; q++) {
            __nv_bfloat16 ha = __float2bfloat16(h[2 * q]);
            __nv_bfloat16 hb = __float2bfloat16(h[2 * q + 1]);
            hv[q] = pack_bf16(__bfloat162float(ha), __bfloat162float(hb));
            lv[q] = pack_bf16(h[2 * q] - __bfloat162float(ha),
                              h[2 * q + 1] - __bfloat162float(hb));
        }
        uint32_t perm = (uint32_t)(cix ^ (r & 3) ^ ((r >> 2) & 1));
        uint32_t d = baseu + (uint32_t)s * G2_STAGE + r * 64 + (perm << 4);
        STS128(d, hv[0], hv[1], hv[2], hv[3]);
        STS128(d + G2_AT, lv[0], lv[1], lv[2], lv[3]);
    };

    auto mma_half = [&](uint32_t stb, uint32_t kx) {
        uint32_t fbh[4][2], fbl[4][2];
#pragma unroll
        for (int j = 0; j < 2; j++) {
            uint32_t b = stb + (boff[j] ^ kx);
            LDSM4(fbh[2 * j][0], fbh[2 * j][1], fbh[2 * j + 1][0], fbh[2 * j + 1][1], b);
            LDSM4(fbl[2 * j][0], fbl[2 * j][1], fbl[2 * j + 1][0], fbl[2 * j + 1][1], b + G2_BT);
        }
#pragma unroll
        for (int mi = 0; mi < 4; mi++) {
            uint32_t fah[4], fal[4];
            uint32_t a = stb + (aoff[mi] ^ kx);
            LDSM4(fah[0], fah[1], fah[2], fah[3], a);
            LDSM4(fal[0], fal[1], fal[2], fal[3], a + G2_AT);
#pragma unroll
            for (int nj = 0; nj < 4; nj++) {
                MMA16816(acc[mi][nj], fah, fbh[nj]);
                MMA16816(acc[mi][nj], fal, fbh[nj]);
                MMA16816(acc[mi][nj], fah, fbl[nj]);
            }
        }
    };

    // Prologue
    {
        if (jb > 0 && tid < 256)
            cp16(baseu + G2_TDOFF + tid * 16, tdrow + tid * 4);
        uint32_t tdst = baseu + G2_TBOFF;  // stage 0
#pragma unroll
        for (int q = 0; q < 2; q++) {
            int idx = q * 512 + tid;
            int row = idx >> 3, ch = idx & 7;
            cp16(tdst + row * G2_TBSTR + ch * 16, bprow + (size_t)row * HX + ch * 4);
        }
        CP_COMMIT();
    }
    issue_group(1, 0);
    issue_group(2, 1);
    CP_WAIT(2);
    __syncthreads();
    convert(0);

    for (int c = 0; c < G2_NCH; c++) {
        CP_WAIT(1);
        __syncthreads();
        uint32_t stb = baseu + (uint32_t)(c % 3) * G2_STAGE;
        mma_half(stb, 0u);
        issue_group(c + 3, c + 2);
        if (c + 1 < G2_NCH) convert(c + 1);
        mma_half(stb, 32u);
    }
    __syncthreads();

    // Epilogue: EX split bf16
    const int r_in = lane >> 2, c2 = (lane & 3) * 2;
#pragma unroll
    for (int mi = 0; mi < 4; mi++) {
        size_t rowA = growBase + warp_m * 64 + mi * 16 + r_in;
        size_t rowB = rowA + 8;
#pragma unroll
        for (int nj = 0; nj < 4; nj++) {
            int col = nbase + warp_n * 32 + nj * 8 + c2;
            float b0 = bias[col], b1 = bias[col + 1];
            float v00 = acc[mi][nj][0] + b0;
            float v01 = acc[mi][nj][1] + b1;
            float v10 = acc[mi][nj][2] + b0;
            float v11 = acc[mi][nj][3] + b1;
            __nv_bfloat16 h00 = __float2bfloat16(v00);
            __nv_bfloat16 h01 = __float2bfloat16(v01);
            __nv_bfloat16 h10 = __float2bfloat16(v10);
            __nv_bfloat16 h11 = __float2bfloat16(v11);
            *(__nv_bfloat162*)(g_EXh + rowA * EX_DIM + col) = __halves2bfloat162(h00, h01);
            *(__nv_bfloat162*)(g_EXh + rowB * EX_DIM + col) = __halves2bfloat162(h10, h11);
            *(__nv_bfloat162*)(g_EXl + rowA * EX_DIM + col) = __halves2bfloat162(
                __float2bfloat16(v00 - __bfloat162float(h00)),
                __float2bfloat16(v01 - __bfloat162float(h01)));
            *(__nv_bfloat162*)(g_EXl + rowB * EX_DIM + col) = __halves2bfloat162(
                __float2bfloat16(v10 - __bfloat162float(h10)),
                __float2bfloat16(v11 - __bfloat162float(h11)));
        }
    }
}

// ---------------------------------------------------------------------------
// GEMM3 (R13-proven): H2pre = EX @ W3T + bb1eff + t*Wb1row0; V-epilogue.
// 256 threads, 8 warps, warp tile 64x32, CTA 128x128, BK=32, 3-stage,
// 2 CTAs/SM, issues interleaved, two barriers per chunk.
// ---------------------------------------------------------------------------
#define G3_NCH 16
#define G3_AT  8192u
#define G3_BT  8192u
#define G3_STAGE (2 * G3_AT + 2 * G3_BT)
#define G3_SMEM  (3 * (int)G3_STAGE + 256)

__global__ void __launch_bounds__(256, 2) gemm3_kernel(
    const float* __restrict__ trow, const float* __restrict__ times_t,
    const float* __restrict__ times_tau, const int* __restrict__ kptr)
{
    extern __shared__ char dsm[];
    char* basep = (char*)(((uintptr_t)dsm + 127) & ~(uintptr_t)127);
    const uint32_t baseu = smem_u32(basep);
    __shared__ float sV[128];

    const int tid  = threadIdx.x;
    const int lane = tid & 31, wid = tid >> 5;
    const int warp_m = wid >> 2, warp_n = wid & 3;
    const size_t growBase = (size_t)blockIdx.y * 128;
    const int nbase = blockIdx.x * 128;

    float acc[4][4][4];
#pragma unroll
    for (int i = 0; i < 4; i++)
#pragma unroll
        for (int j = 0; j < 4; j++)
#pragma unroll
            for (int v = 0; v < 4; v++) acc[i][j][v] = 0.f;

    uint32_t aoff[4];
    {
        int r16 = lane & 15, half = lane >> 4;
#pragma unroll
        for (int i = 0; i < 4; i++) {
            int row = warp_m * 64 + i * 16 + r16;
            int perm = half ^ (row & 3) ^ ((row >> 2) & 1);
            aoff[i] = row * 64 + (perm << 4);
        }
    }
    uint32_t boff[2];
    {
        int rn = (lane >> 4) * 8 + (lane & 7);
        int c  = (lane >> 3) & 1;
#pragma unroll
        for (int j = 0; j < 2; j++) {
            int row = warp_n * 32 + j * 16 + rn;
            int perm = c ^ (row & 3) ^ ((row >> 2) & 1);
            boff[j] = 2 * G3_AT + row * 64 + (perm << 4);
        }
    }

    auto load_chunk = [&](int cc) {
        uint32_t tb = baseu + (uint32_t)(cc % 3) * G3_STAGE;
        int k0 = cc * 32;
#pragma unroll
        for (int it = 0; it < 2; it++) {
            int idx = it * 256 + tid;
            int r = idx >> 2, c = idx & 3;
            uint32_t perm = (uint32_t)(c ^ (r & 3) ^ ((r >> 2) & 1));
            uint32_t d = tb + r * 64 + (perm << 4);
            cp16(d, g_EXh + (growBase + r) * EX_DIM + k0 + c * 8);
            cp16(d + G3_AT, g_EXl + (growBase + r) * EX_DIM + k0 + c * 8);
        }
#pragma unroll
        for (int it = 0; it < 2; it++) {
            int idx = it * 256 + tid;
            int r = idx >> 2, c = idx & 3;
            uint32_t perm = (uint32_t)(c ^ (r & 3) ^ ((r >> 2) & 1));
            uint32_t d = tb + 2 * G3_AT + r * 64 + (perm << 4);
            cp16(d, g_W3Th + (size_t)(nbase + r) * EX_DIM + k0 + c * 8);
            cp16(d + G3_BT, g_W3Tl + (size_t)(nbase + r) * EX_DIM + k0 + c * 8);
        }
        CP_COMMIT();
    };

    auto mma_half = [&](uint32_t tb, uint32_t kx) {
        uint32_t fbh[2][2], fbl[2][2];
        uint32_t b0a = tb + (boff[0] ^ kx);
        LDSM4(fbh[0][0], fbh[0][1], fbh[1][0], fbh[1][1], b0a);
        LDSM4(fbl[0][0], fbl[0][1], fbl[1][0], fbl[1][1], b0a + G3_BT);
#pragma unroll
        for (int mi = 0; mi < 4; mi++) {
            uint32_t fah[4], fal[4];
            uint32_t a = tb + (aoff[mi] ^ kx);
            LDSM4(fah[0], fah[1], fah[2], fah[3], a);
            LDSM4(fal[0], fal[1], fal[2], fal[3], a + G3_AT);
#pragma unroll
            for (int nj = 0; nj < 2; nj++) {
                MMA16816(acc[mi][nj], fah, fbh[nj]);
                MMA16816(acc[mi][nj], fal, fbh[nj]);
                MMA16816(acc[mi][nj], fah, fbl[nj]);
            }
        }
        uint32_t b1a = tb + (boff[1] ^ kx);
        LDSM4(fbh[0][0], fbh[0][1], fbh[1][0], fbh[1][1], b1a);
        LDSM4(fbl[0][0], fbl[0][1], fbl[1][0], fbl[1][1], b1a + G3_BT);
#pragma unroll
        for (int mi = 0; mi < 4; mi++) {
            uint32_t fah[4], fal[4];
            uint32_t a = tb + (aoff[mi] ^ kx);
            LDSM4(fah[0], fah[1], fah[2], fah[3], a);
            LDSM4(fal[0], fal[1], fal[2], fal[3], a + G3_AT);
#pragma unroll
            for (int nj = 0; nj < 2; nj++) {
                MMA16816(acc[mi][nj + 2], fah, fbh[nj]);
                MMA16816(acc[mi][nj + 2], fal, fbh[nj]);
                MMA16816(acc[mi][nj + 2], fah, fbl[nj]);
            }
        }
    };

    load_chunk(0);
    load_chunk(1);

    for (int ch = 0; ch < G3_NCH; ch++) {
        CP_WAIT(1);
        __syncthreads();
        uint32_t tb = baseu + (uint32_t)(ch % 3) * G3_STAGE;
        mma_half(tb, 0u);
        if (ch + 2 < G3_NCH) load_chunk(ch + 2);
        else CP_COMMIT();
        mma_half(tb, 32u);
        __syncthreads();
    }

    // V-reduction epilogue
    const int r_in = lane >> 2, c2 = (lane & 3) * 2;
    if (tid < 128) sV[tid] = 0.f;
    __syncthreads();
    float tb0 = times_t[read_int(kptr)];
    float cA[4], cB[4], tAv[4], tBv[4];
#pragma unroll
    for (int mi = 0; mi < 4; mi++) {
        size_t rowA = growBase + warp_m * 64 + mi * 16 + r_in;
        cA[mi] = g_coeff[rowA];
        cB[mi] = g_coeff[rowA + 8];
        tAv[mi] = tb0 + times_tau[rowA & 255];
        tBv[mi] = tb0 + times_tau[(rowA + 8) & 255];
    }
#pragma unroll
    for (int nj = 0; nj < 4; nj++) {
        int colL = warp_n * 32 + ((nj >> 1) * 16) + (nj & 1) * 8 + c2;
        int col  = nbase + colL;
        float b0 = g_bb1eff[col], b1 = g_bb1eff[col + 1];
        float tr0 = trow[col], tr1 = trow[col + 1];
        float p0 = 0.f, p1 = 0.f;
#pragma unroll
        for (int mi = 0; mi < 4; mi++) {
            float v00 = fast_tanh(fmaf(tAv[mi], tr0, acc[mi][nj][0] + b0));
            float v01 = fast_tanh(fmaf(tAv[mi], tr1, acc[mi][nj][1] + b1));
            float v10 = fast_tanh(fmaf(tBv[mi], tr0, acc[mi][nj][2] + b0));
            float v11 = fast_tanh(fmaf(tBv[mi], tr1, acc[mi][nj][3] + b1));
            p0 += cA[mi] * v00 + cB[mi] * v10;
            p1 += cA[mi] * v01 + cB[mi] * v11;
        }
#pragma unroll
        for (int off = 4; off <= 16; off <<= 1) {
            p0 += __shfl_xor_sync(0xFFFFFFFFu, p0, off);
            p1 += __shfl_xor_sync(0xFFFFFFFFu, p1, off);
        }
        if (lane < 4) {
            atomicAdd(&sV[colL], p0);
            atomicAdd(&sV[colL + 1], p1);
        }
    }
    __syncthreads();
    if (tid < 128)
        g_Vpart[(size_t)blockIdx.y * HB + nbase + tid] = sV[tid];
}

// ---------------------------------------------------------------------------
// v_sum / final_si
// ---------------------------------------------------------------------------
__global__ void v_sum(const float* __restrict__ Wb2) {
    __shared__ float V[256];
    __shared__ float red[256];
    int tid = threadIdx.x;
    int hb = blockIdx.x * 256 + tid;
    float s = 0.f;
    for (int p = 0; p < MTILES; p++) s += g_Vpart[(size_t)p * HB + hb];
    V[tid] = s;
    __syncthreads();
    int g = tid & 63, c4 = tid >> 6;
    float acc = 0.f;
    for (int hh = c4 * 64; hh < c4 * 64 + 64; hh++)
        acc += V[hh] * Wb2[(size_t)(blockIdx.x * 256 + hh) * GOUT + g];
    red[tid] = acc;
    __syncthreads();
    if (tid < 64)
        g_sipart[blockIdx.x * GOUT + tid] =
            red[tid] + red[tid + 64] + red[tid + 128] + red[tid + 192];
}

__global__ void final_si(float* __restrict__ out) {
    int g = threadIdx.x;
    float acc = 0.f;
#pragma unroll
    for (int c = 0; c < 8; c++) acc += g_sipart[c * GOUT + g];
    out[g] = acc;
}

// ---------------------------------------------------------------------------
// Launch. ncu profiles 0-based launch index 3 -> gemm2.
// ---------------------------------------------------------------------------
extern "C" void kernel_launch(void* const* d_in, const int* in_sizes, int n_in,
                              void* d_out, int out_size) {
    const float* X         = (const float*)d_in[0];
    const float* Y         = (const float*)d_in[1];
    const float* R         = (const float*)d_in[2];
    const float* stoich    = (const float*)d_in[3];
    const float* times_t   = (const float*)d_in[4];
    const float* times_tau = (const float*)d_in[5];
    const float* Wx1       = (const float*)d_in[6];
    const float* bx1       = (const float*)d_in[7];
    const float* Wx2       = (const float*)d_in[8];
    const float* bx2       = (const float*)d_in[9];
    const float* Wih       = (const float*)d_in[10];
    const float* Whh       = (const float*)d_in[11];
    const float* bh        = (const float*)d_in[12];
    const float* Wb1       = (const float*)d_in[13];
    const float* bb1       = (const float*)d_in[14];
    const float* Wb2       = (const float*)d_in[15];
    const int*   kptr      = (const int*)d_in[17];
    const int*   kpptr     = (const int*)d_in[18];
    const int*   qptr      = (const int*)d_in[19];
    const int*   qpptr     = (const int*)d_in[20];
    float* out = (float*)d_out;

    cudaFuncSetAttribute(gemm2_kernel,
                         cudaFuncAttributeMaxDynamicSharedMemorySize, G2_SMEM);
    cudaFuncSetAttribute(gemm3_kernel,
                         cudaFuncAttributeMaxDynamicSharedMemorySize, G3_SMEM);

    prep_w<<<512, dim3(32, 8)>>>(Wx2, 0);                            // 0
    prep_w<<<1024, dim3(32, 8)>>>(Wb1, 1);                           // 1
    pre_h1_kernel<<<MBAR + MR, 256>>>(X, stoich, Wx1, bx1,           // 2
                                      kpptr, qpptr);
    gemm2_kernel<<<dim3(2, 135), 512, G2_SMEM>>>(                    // 3 (ncu)
        bx2, Y, Wih, Whh, bh, kptr, qptr, X, R, stoich, kpptr, qpptr);
    bb1eff_kernel<<<8, 256>>>(Wb1, bb1);                             // 4
    gemm3_kernel<<<dim3(16, MTILES), 256, G3_SMEM>>>(                // 5
        Wb1, times_t, times_tau, kptr);
    v_sum<<<8, 256>>>(Wb2);                                          // 6
    final_si<<<1, 64>>>(out);                                        // 7
}

// round 17
// speedup vs baseline: 1.0160x; 1.0160x over previous
#include <cuda_runtime.h>
#include <cuda_bf16.h>
#include <cstdint>

// ---------------------------------------------------------------------------
// Problem constants
// ---------------------------------------------------------------------------
#define DX      16
#define DY      8
#define MR      64
#define MBAR    256
#define NT      9
#define GOUT    64
#define HX      1024
#define EX_DIM  512
#define HRNN    512
#define HB      2048
#define TOTAL   2049
#define M_TOTAL 16640           // (MR+1)*MBAR
#define MTILES  130             // M_TOTAL / 128

// ---------------------------------------------------------------------------
// Scratch (__device__ globals; referenced ONLY from device code)
// ---------------------------------------------------------------------------
__device__ __nv_bfloat16 g_EXh[(size_t)M_TOTAL * EX_DIM];
__device__ __nv_bfloat16 g_EXl[(size_t)M_TOTAL * EX_DIM];
__device__ __nv_bfloat16 g_W2Th[EX_DIM * HX],  g_W2Tl[EX_DIM * HX];   // [n][k]
__device__ __nv_bfloat16 g_W3Th[HB * EX_DIM],  g_W3Tl[HB * EX_DIM];   // [n][k]
__device__ float g_h0[HRNN], g_h1buf[HRNN];
__device__ float g_bb1eff[HB];
__device__ float g_Tb[MBAR * HX];        // tanh(basepre) (bx1 folded in)
__device__ float g_Td[MR * HX];          // tanh(delta_j)
__device__ float g_coeff[M_TOTAL];       // signed reduction weights per row
__device__ float g_Vpart[(size_t)MTILES * HB];
__device__ float g_sipart[8 * GOUT];
__device__ int   g_sync[16];             // rnn cross-CTA step barrier counters

__device__ __forceinline__ int read_int(const int* p) {
    int v = *p;
    if (v >= 0 && v < (1 << 20)) return v;
    return (int)__int_as_float(v);
}

// Fast tanh: 1 - 2/(e^{2x}+1). ~1e-6 abs err.
__device__ __forceinline__ float fast_tanh(float x) {
    float e = __expf(2.f * x);
    return 1.f - __fdividef(2.f, e + 1.f);
}

// ---------------------------------------------------------------------------
// PTX helpers
// ---------------------------------------------------------------------------
__device__ __forceinline__ uint32_t smem_u32(const void* p) {
    uint32_t a;
    asm("{ .reg .u64 t; cvta.to.shared.u64 t, %1; cvt.u32.u64 %0, t; }"
        : "=r"(a) : "l"(p));
    return a;
}
__device__ __forceinline__ void cp16(uint32_t dst, const void* src) {
    asm volatile("cp.async.cg.shared.global [%0], [%1], 16;"
                 :: "r"(dst), "l"(src) : "memory");
}
#define CP_COMMIT() asm volatile("cp.async.commit_group;" ::: "memory")
#define CP_WAIT(n)  asm volatile("cp.async.wait_group %0;" :: "n"(n) : "memory")

#define STS128(addr, w0, w1, w2, w3)                                           \
    asm volatile("st.shared.v4.b32 [%0], {%1,%2,%3,%4};"                       \
                 :: "r"(addr), "r"(w0), "r"(w1), "r"(w2), "r"(w3) : "memory")

#define LDSM4(r0, r1, r2, r3, addr)                                            \
    asm volatile("ldmatrix.sync.aligned.m8n8.x4.shared.b16 {%0,%1,%2,%3}, [%4];" \
                 : "=r"(r0), "=r"(r1), "=r"(r2), "=r"(r3) : "r"(addr))

#define MMA16816(d, a, b)                                                      \
    asm volatile("mma.sync.aligned.m16n8k16.row.col.f32.bf16.bf16.f32 "        \
                 "{%0,%1,%2,%3}, {%4,%5,%6,%7}, {%8,%9}, {%0,%1,%2,%3};"       \
                 : "+f"((d)[0]), "+f"((d)[1]), "+f"((d)[2]), "+f"((d)[3])      \
                 : "r"((a)[0]), "r"((a)[1]), "r"((a)[2]), "r"((a)[3]),         \
                   "r"((b)[0]), "r"((b)[1]))

__device__ __forceinline__ uint32_t pack_bf16(float a, float b) {
    __nv_bfloat162 t = __halves2bfloat162(__float2bfloat16(a), __float2bfloat16(b));
    return *(uint32_t*)&t;
}

// ---------------------------------------------------------------------------
// Weight prep (two launches to keep gemm2 at ncu launch index 3).
// which==0: Wx2 -> W2T (512 blocks) + zero g_sync.
// which==1: Wb1[1:513] -> W3T (1024 blocks).
// ---------------------------------------------------------------------------
__global__ void prep_w(const float* __restrict__ src, int which) {
    if (which == 0 && blockIdx.x == 0 && threadIdx.y == 0 && threadIdx.x < 16)
        g_sync[threadIdx.x] = 0;
    int b = blockIdx.x;
    int srcStride, rowOff, Kdim, kt, nt;
    __nv_bfloat16 *dh, *dl;
    if (which == 0) {
        srcStride = EX_DIM; rowOff = 0; Kdim = HX;
        dh = g_W2Th; dl = g_W2Tl; kt = b & 31; nt = b >> 5;
    } else {
        srcStride = HB; rowOff = 1; Kdim = EX_DIM;
        dh = g_W3Th; dl = g_W3Tl; kt = b & 15; nt = b >> 4;
    }
    int kb = kt * 32, nb = nt * 32;
    __shared__ float t[32][33];
    int tx = threadIdx.x, ty = threadIdx.y;
#pragma unroll
    for (int dy = 0; dy < 32; dy += 8)
        t[ty + dy][tx] = src[(size_t)(rowOff + kb + ty + dy) * srcStride + nb + tx];
    __syncthreads();
#pragma unroll
    for (int dy = 0; dy < 32; dy += 8) {
        int n = nb + ty + dy, k = kb + tx;
        float v = t[tx][ty + dy];
        __nv_bfloat16 h = __float2bfloat16(v);
        dh[(size_t)n * Kdim + k] = h;
        dl[(size_t)n * Kdim + k] = __float2bfloat16(v - __bfloat162float(h));
    }
}

// bb1_eff[n] = bb1[n] + sum_h eY[h] * Wb1[513+h][n]
__global__ void bb1eff_kernel(const float* __restrict__ Wb1,
                              const float* __restrict__ bb1) {
    int n = blockIdx.x * 256 + threadIdx.x;
    float acc = bb1[n];
    const float* w = Wb1 + (size_t)(1 + EX_DIM) * HB + n;
#pragma unroll 8
    for (int h = 0; h < HRNN; h++) acc += g_h0[h] * w[(size_t)h * HB];
    g_bb1eff[n] = acc;
}

// ---------------------------------------------------------------------------
// Pre-activations -> TANH: rows 0..255 -> Tb, rows 256..319 -> Td
// ---------------------------------------------------------------------------
__global__ void pre_h1_kernel(const float* __restrict__ X,
                              const float* __restrict__ stoich,
                              const float* __restrict__ Wx1,
                              const float* __restrict__ bx1,
                              const int* kpp, const int* qpp) {
    __shared__ float xv[DX];
    int row = blockIdx.x;        // 0..319
    int tid = threadIdx.x;
    int kp = read_int(kpp), qp = read_int(qpp);
    int base = kp * MBAR;
    if (tid < DX) {
        xv[tid] = (row < MBAR)
            ? X[((size_t)qp * TOTAL + base + row) * DX + tid]
            : stoich[tid * MR + (row - MBAR)];
    }
    __syncthreads();
#pragma unroll
    for (int ci = 0; ci < 4; ci++) {
        int col = ci * 256 + tid;
        float acc = (row < MBAR) ? bx1[col] : 0.f;
#pragma unroll
        for (int d = 0; d < DX; d++) acc = fmaf(xv[d], Wx1[d * HX + col], acc);
        float t = fast_tanh(acc);
        if (row < MBAR) g_Tb[row * HX + col] = t;
        else            g_Td[(row - MBAR) * HX + col] = t;
    }
}

// ---------------------------------------------------------------------------
// GEMM2 + piggybacked tails.  Grid (2, 135):
//   y in 0..3          -> 8 RNN CTAs (r = y*2+x): 64 units per CTA, 8 K-slice
//                          threads per unit laid out COALESCED (sub = tid>>6,
//                          ul = tid&63; warp = 32 consecutive units, one
//                          K-slice -> every Whh load is one 128B line,
//                          hprev is warp-uniform broadcast). smem reduction
//                          folds the 8 K-slices. Cross-CTA spin barrier via
//                          g_sync (zeroed in prep0; first CTAs dispatched ->
//                          co-resident).
//   (x,y) == (0,4)     -> coeff (disp + base) in one CTA, per-thread
//   (x,y) == (1,4)     -> idle
//   y >= 5             -> GEMM tile row (y-5); EX = H1 @ W2T + bx2 with
//                          H1 = (Tb+Td)/(1+Tb*Td) computed in-kernel.
// GEMM config: 512 threads, 16 warps (2x8), warp tile 64x32, CTA 128x256,
// BK=32, 3-stage pipeline, issues interleaved, single barrier per chunk.
// ---------------------------------------------------------------------------
#define G2_NCH   32
#define G2_AT    8192u
#define G2_BT    16384u
#define G2_TBOFF 49152u
#define G2_TBSTR 144
#define G2_STAGE 67584u
#define G2_TDOFF (3u * G2_STAGE)
#define G2_SMEM  (3 * 67584 + 4096 + 128)

__global__ void __launch_bounds__(512, 1) gemm2_kernel(
    const float* __restrict__ bias,
    const float* __restrict__ Y,   const float* __restrict__ Wih,
    const float* __restrict__ Whh, const float* __restrict__ bh,
    const int* kptr, const int* qptr,
    const float* __restrict__ X,   const float* __restrict__ R,
    const float* __restrict__ stoich,
    const int* kpp, const int* qpp)
{
    const int tid = threadIdx.x;

    // ---------------- piggybacked tails ----------------
    if (blockIdx.y < 5) {
        if (blockIdx.y < 4) {
            // RNN CTA r: units [r*64, r*64+64), coalesced K-slice layout.
            __shared__ float spart[512];
            int r = (int)(blockIdx.y * 2 + blockIdx.x);
            int k = read_int(kptr), q = read_int(qptr);
            int steps = NT - 1 - k;
            int sub = tid >> 6, ul = tid & 63;
            int i = r * 64 + ul;
            float hlast = 0.f;
            for (int s = 0; s < steps; s++) {
                float partial = 0.f;
                if (s > 0) {
                    const float* hprev = (s & 1) ? g_h1buf : g_h0;
                    const float* hp = hprev + sub * 64;
                    const float* wrow = Whh + (size_t)(sub * 64) * HRNN + i;
#pragma unroll 8
                    for (int kk = 0; kk < 64; kk++)
                        partial = fmaf(hp[kk], wrow[(size_t)kk * HRNN], partial);
                }
                spart[tid] = partial;
                __syncthreads();
                if (tid < 64) {
                    float acc = 0.f;
#pragma unroll
                    for (int ss = 0; ss < 8; ss++) acc += spart[ss * 64 + tid];
                    int iu = r * 64 + tid;
                    const float* y = Y + ((size_t)q * NT + (k + 1 + s)) * DY;
                    float a2 = bh[iu] + acc;
#pragma unroll
                    for (int d = 0; d < DY; d++)
                        a2 += y[d] * Wih[d * HRNN + iu];
                    hlast = fast_tanh(a2);
                    float* out = (s & 1) ? g_h0 : g_h1buf;
                    out[iu] = hlast;
                }
                __threadfence();
                __syncthreads();
                if (tid == 0) {
                    atomicAdd(&g_sync[s], 1);
                    while (((volatile int*)g_sync)[s] < 8)
                        asm volatile("nanosleep.u32 32;");
                }
                __syncthreads();
                __threadfence();
            }
            if (tid < 64) g_h0[r * 64 + tid] = hlast;
        } else if (blockIdx.x == 0 && tid < 256) {
            // coeff: per-thread over m, loop over j; base row folded in.
            int m = tid;
            int kp = read_int(kpp), qp = read_int(qpp);
            int base = kp * MBAR;
            float xr[DX];
#pragma unroll
            for (int d = 0; d < DX; d++)
                xr[d] = X[((size_t)qp * TOTAL + base + m) * DX + d];
            const float* R0 = R + ((size_t)qp * TOTAL + base + m) * MR;
            float bsum = 0.f;
            for (int j = 0; j < MR; j++) {
                bool valid = true;
#pragma unroll
                for (int d = 0; d < DX; d++)
                    valid = valid && (xr[d] + stoich[d * MR + j] >= 0.f);
                float w = valid ? (R0[MR + j] - R0[j]) : 0.f;
                g_coeff[(j + 1) * MBAR + m] = w;
                bsum += w;
            }
            g_coeff[m] = -bsum;
        }
        return;
    }

    // ---------------- GEMM tile path ----------------
    extern __shared__ char dsm[];
    char* basep = (char*)(((uintptr_t)dsm + 127) & ~(uintptr_t)127);
    const uint32_t baseu = smem_u32(basep);

    const int ty = (int)blockIdx.y - 5;            // 0..129
    const int lane = tid & 31, wid = tid >> 5;
    const int warp_m = wid >> 3, warp_n = wid & 7;
    const size_t growBase = (size_t)ty * 128;
    const int nbase = blockIdx.x * 256;
    const int jb = ty >> 1;
    const float* bprow = g_Tb + (size_t)((ty & 1) * 128) * HX;
    const float* tdrow = (jb > 0) ? (g_Td + (size_t)(jb - 1) * HX) : nullptr;

    float acc[4][4][4];
#pragma unroll
    for (int i = 0; i < 4; i++)
#pragma unroll
        for (int j = 0; j < 4; j++)
#pragma unroll
            for (int v = 0; v < 4; v++) acc[i][j][v] = 0.f;

    uint32_t aoff[4];
    {
        int r16 = lane & 15, half = lane >> 4;
#pragma unroll
        for (int i = 0; i < 4; i++) {
            int row = warp_m * 64 + i * 16 + r16;
            int perm = half ^ (row & 3) ^ ((row >> 2) & 1);
            aoff[i] = row * 64 + (perm << 4);
        }
    }
    uint32_t boff[2];
    {
        int rn = (lane >> 4) * 8 + (lane & 7);
        int c  = (lane >> 3) & 1;
#pragma unroll
        for (int j = 0; j < 2; j++) {
            int row = warp_n * 32 + j * 16 + rn;
            int perm = c ^ (row & 3) ^ ((row >> 2) & 1);
            boff[j] = 2 * G2_AT + row * 64 + (perm << 4);
        }
    }

    const int cix = tid & 3;

    auto issue_group = [&](int tb_c, int b_c) {
        if (tb_c < G2_NCH) {
            uint32_t tdst = baseu + (uint32_t)(tb_c % 3) * G2_STAGE + G2_TBOFF;
            int k0 = tb_c * 32;
#pragma unroll
            for (int q = 0; q < 2; q++) {
                int idx = q * 512 + tid;
                int row = idx >> 3, ch = idx & 7;
                cp16(tdst + row * G2_TBSTR + ch * 16,
                     bprow + (size_t)row * HX + k0 + ch * 4);
            }
        }
        if (b_c < G2_NCH) {
            uint32_t tb2 = baseu + (uint32_t)(b_c % 3) * G2_STAGE;
            int k0 = b_c * 32;
#pragma unroll
            for (int it = 0; it < 2; it++) {
                int idx = it * 512 + tid;
                int r = idx >> 2, c2 = idx & 3;
                uint32_t perm = (uint32_t)(c2 ^ (r & 3) ^ ((r >> 2) & 1));
                uint32_t d = tb2 + 2 * G2_AT + r * 64 + (perm << 4);
                cp16(d, g_W2Th + (size_t)(nbase + r) * HX + k0 + c2 * 8);
                cp16(d + G2_BT, g_W2Tl + (size_t)(nbase + r) * HX + k0 + c2 * 8);
            }
        }
        CP_COMMIT();
    };

    auto convert = [&](int tc) {
        int s = tc % 3;
        int r = tid >> 2;   // 0..127
        float td[8];
        if (jb > 0) {
            const float* tdp = (const float*)(basep + G2_TDOFF) + tc * 32 + cix * 8;
            float4 t0 = *(const float4*)tdp;
            float4 t1 = *(const float4*)(tdp + 4);
            td[0] = t0.x; td[1] = t0.y; td[2] = t0.z; td[3] = t0.w;
            td[4] = t1.x; td[5] = t1.y; td[6] = t1.z; td[7] = t1.w;
        }
        const float* tbp = (const float*)(basep + (size_t)s * G2_STAGE + G2_TBOFF
                                          + (size_t)r * G2_TBSTR) + cix * 8;
        float4 b0 = *(const float4*)tbp;
        float4 b1 = *(const float4*)(tbp + 4);
        float tb[8] = {b0.x, b0.y, b0.z, b0.w, b1.x, b1.y, b1.z, b1.w};
        float h[8];
        if (jb > 0) {
#pragma unroll
            for (int e = 0; e < 8; e++)
                h[e] = __fdividef(tb[e] + td[e], fmaf(tb[e], td[e], 1.f));
        } else {
#pragma unroll
            for (int e = 0; e < 8; e++) h[e] = tb[e];
        }
        uint32_t hv[4], lv[4];
#pragma unroll
        for (int q = 0; q < 4; q++) {
            __nv_bfloat16 ha = __float2bfloat16(h[2 * q]);
            __nv_bfloat16 hb = __float2bfloat16(h[2 * q + 1]);
            hv[q] = pack_bf16(__bfloat162float(ha), __bfloat162float(hb));
            lv[q] = pack_bf16(h[2 * q] - __bfloat162float(ha),
                              h[2 * q + 1] - __bfloat162float(hb));
        }
        uint32_t perm = (uint32_t)(cix ^ (r & 3) ^ ((r >> 2) & 1));
        uint32_t d = baseu + (uint32_t)s * G2_STAGE + r * 64 + (perm << 4);
        STS128(d, hv[0], hv[1], hv[2], hv[3]);
        STS128(d + G2_AT, lv[0], lv[1], lv[2], lv[3]);
    };

    auto mma_half = [&](uint32_t stb, uint32_t kx) {
        uint32_t fbh[4][2], fbl[4][2];
#pragma unroll
        for (int j = 0; j < 2; j++) {
            uint32_t b = stb + (boff[j] ^ kx);
            LDSM4(fbh[2 * j][0], fbh[2 * j][1], fbh[2 * j + 1][0], fbh[2 * j + 1][1], b);
            LDSM4(fbl[2 * j][0], fbl[2 * j][1], fbl[2 * j + 1][0], fbl[2 * j + 1][1], b + G2_BT);
        }
#pragma unroll
        for (int mi = 0; mi < 4; mi++) {
            uint32_t fah[4], fal[4];
            uint32_t a = stb + (aoff[mi] ^ kx);
            LDSM4(fah[0], fah[1], fah[2], fah[3], a);
            LDSM4(fal[0], fal[1], fal[2], fal[3], a + G2_AT);
#pragma unroll
            for (int nj = 0; nj < 4; nj++) {
                MMA16816(acc[mi][nj], fah, fbh[nj]);
                MMA16816(acc[mi][nj], fal, fbh[nj]);
                MMA16816(acc[mi][nj], fah, fbl[nj]);
            }
        }
    };

    // Prologue
    {
        if (jb > 0 && tid < 256)
            cp16(baseu + G2_TDOFF + tid * 16, tdrow + tid * 4);
        uint32_t tdst = baseu + G2_TBOFF;  // stage 0
#pragma unroll
        for (int q = 0; q < 2; q++) {
            int idx = q * 512 + tid;
            int row = idx >> 3, ch = idx & 7;
            cp16(tdst + row * G2_TBSTR + ch * 16, bprow + (size_t)row * HX + ch * 4);
        }
        CP_COMMIT();
    }
    issue_group(1, 0);
    issue_group(2, 1);
    CP_WAIT(2);
    __syncthreads();
    convert(0);

    for (int c = 0; c < G2_NCH; c++) {
        CP_WAIT(1);
        __syncthreads();
        uint32_t stb = baseu + (uint32_t)(c % 3) * G2_STAGE;
        mma_half(stb, 0u);
        issue_group(c + 3, c + 2);
        if (c + 1 < G2_NCH) convert(c + 1);
        mma_half(stb, 32u);
    }
    __syncthreads();

    // Epilogue: EX split bf16
    const int r_in = lane >> 2, c2 = (lane & 3) * 2;
#pragma unroll
    for (int mi = 0; mi < 4; mi++) {
        size_t rowA = growBase + warp_m * 64 + mi * 16 + r_in;
        size_t rowB = rowA + 8;
#pragma unroll
        for (int nj = 0; nj < 4; nj++) {
            int col = nbase + warp_n * 32 + nj * 8 + c2;
            float b0 = bias[col], b1 = bias[col + 1];
            float v00 = acc[mi][nj][0] + b0;
            float v01 = acc[mi][nj][1] + b1;
            float v10 = acc[mi][nj][2] + b0;
            float v11 = acc[mi][nj][3] + b1;
            __nv_bfloat16 h00 = __float2bfloat16(v00);
            __nv_bfloat16 h01 = __float2bfloat16(v01);
            __nv_bfloat16 h10 = __float2bfloat16(v10);
            __nv_bfloat16 h11 = __float2bfloat16(v11);
            *(__nv_bfloat162*)(g_EXh + rowA * EX_DIM + col) = __halves2bfloat162(h00, h01);
            *(__nv_bfloat162*)(g_EXh + rowB * EX_DIM + col) = __halves2bfloat162(h10, h11);
            *(__nv_bfloat162*)(g_EXl + rowA * EX_DIM + col) = __halves2bfloat162(
                __float2bfloat16(v00 - __bfloat162float(h00)),
                __float2bfloat16(v01 - __bfloat162float(h01)));
            *(__nv_bfloat162*)(g_EXl + rowB * EX_DIM + col) = __halves2bfloat162(
                __float2bfloat16(v10 - __bfloat162float(h10)),
                __float2bfloat16(v11 - __bfloat162float(h11)));
        }
    }
}

// ---------------------------------------------------------------------------
// GEMM3 (R13-proven): H2pre = EX @ W3T + bb1eff + t*Wb1row0; V-epilogue.
// 256 threads, 8 warps, warp tile 64x32, CTA 128x128, BK=32, 3-stage,
// 2 CTAs/SM, issues interleaved, two barriers per chunk.
// ---------------------------------------------------------------------------
#define G3_NCH 16
#define G3_AT  8192u
#define G3_BT  8192u
#define G3_STAGE (2 * G3_AT + 2 * G3_BT)
#define G3_SMEM  (3 * (int)G3_STAGE + 256)

__global__ void __launch_bounds__(256, 2) gemm3_kernel(
    const float* __restrict__ trow, const float* __restrict__ times_t,
    const float* __restrict__ times_tau, const int* __restrict__ kptr)
{
    extern __shared__ char dsm[];
    char* basep = (char*)(((uintptr_t)dsm + 127) & ~(uintptr_t)127);
    const uint32_t baseu = smem_u32(basep);
    __shared__ float sV[128];

    const int tid  = threadIdx.x;
    const int lane = tid & 31, wid = tid >> 5;
    const int warp_m = wid >> 2, warp_n = wid & 3;
    const size_t growBase = (size_t)blockIdx.y * 128;
    const int nbase = blockIdx.x * 128;

    float acc[4][4][4];
#pragma unroll
    for (int i = 0; i < 4; i++)
#pragma unroll
        for (int j = 0; j < 4; j++)
#pragma unroll
            for (int v = 0; v < 4; v++) acc[i][j][v] = 0.f;

    uint32_t aoff[4];
    {
        int r16 = lane & 15, half = lane >> 4;
#pragma unroll
        for (int i = 0; i < 4; i++) {
            int row = warp_m * 64 + i * 16 + r16;
            int perm = half ^ (row & 3) ^ ((row >> 2) & 1);
            aoff[i] = row * 64 + (perm << 4);
        }
    }
    uint32_t boff[2];
    {
        int rn = (lane >> 4) * 8 + (lane & 7);
        int c  = (lane >> 3) & 1;
#pragma unroll
        for (int j = 0; j < 2; j++) {
            int row = warp_n * 32 + j * 16 + rn;
            int perm = c ^ (row & 3) ^ ((row >> 2) & 1);
            boff[j] = 2 * G3_AT + row * 64 + (perm << 4);
        }
    }

    auto load_chunk = [&](int cc) {
        uint32_t tb = baseu + (uint32_t)(cc % 3) * G3_STAGE;
        int k0 = cc * 32;
#pragma unroll
        for (int it = 0; it < 2; it++) {
            int idx = it * 256 + tid;
            int r = idx >> 2, c = idx & 3;
            uint32_t perm = (uint32_t)(c ^ (r & 3) ^ ((r >> 2) & 1));
            uint32_t d = tb + r * 64 + (perm << 4);
            cp16(d, g_EXh + (growBase + r) * EX_DIM + k0 + c * 8);
            cp16(d + G3_AT, g_EXl + (growBase + r) * EX_DIM + k0 + c * 8);
        }
#pragma unroll
        for (int it = 0; it < 2; it++) {
            int idx = it * 256 + tid;
            int r = idx >> 2, c = idx & 3;
            uint32_t perm = (uint32_t)(c ^ (r & 3) ^ ((r >> 2) & 1));
            uint32_t d = tb + 2 * G3_AT + r * 64 + (perm << 4);
            cp16(d, g_W3Th + (size_t)(nbase + r) * EX_DIM + k0 + c * 8);
            cp16(d + G3_BT, g_W3Tl + (size_t)(nbase + r) * EX_DIM + k0 + c * 8);
        }
        CP_COMMIT();
    };

    auto mma_half = [&](uint32_t tb, uint32_t kx) {
        uint32_t fbh[2][2], fbl[2][2];
        uint32_t b0a = tb + (boff[0] ^ kx);
        LDSM4(fbh[0][0], fbh[0][1], fbh[1][0], fbh[1][1], b0a);
        LDSM4(fbl[0][0], fbl[0][1], fbl[1][0], fbl[1][1], b0a + G3_BT);
#pragma unroll
        for (int mi = 0; mi < 4; mi++) {
            uint32_t fah[4], fal[4];
            uint32_t a = tb + (aoff[mi] ^ kx);
            LDSM4(fah[0], fah[1], fah[2], fah[3], a);
            LDSM4(fal[0], fal[1], fal[2], fal[3], a + G3_AT);
#pragma unroll
            for (int nj = 0; nj < 2; nj++) {
                MMA16816(acc[mi][nj], fah, fbh[nj]);
                MMA16816(acc[mi][nj], fal, fbh[nj]);
                MMA16816(acc[mi][nj], fah, fbl[nj]);
            }
        }
        uint32_t b1a = tb + (boff[1] ^ kx);
        LDSM4(fbh[0][0], fbh[0][1], fbh[1][0], fbh[1][1], b1a);
        LDSM4(fbl[0][0], fbl[0][1], fbl[1][0], fbl[1][1], b1a + G3_BT);
#pragma unroll
        for (int mi = 0; mi < 4; mi++) {
            uint32_t fah[4], fal[4];
            uint32_t a = tb + (aoff[mi] ^ kx);
            LDSM4(fah[0], fah[1], fah[2], fah[3], a);
            LDSM4(fal[0], fal[1], fal[2], fal[3], a + G3_AT);
#pragma unroll
            for (int nj = 0; nj < 2; nj++) {
                MMA16816(acc[mi][nj + 2], fah, fbh[nj]);
                MMA16816(acc[mi][nj + 2], fal, fbh[nj]);
                MMA16816(acc[mi][nj + 2], fah, fbl[nj]);
            }
        }
    };

    load_chunk(0);
    load_chunk(1);

    for (int ch = 0; ch < G3_NCH; ch++) {
        CP_WAIT(1);
        __syncthreads();
        uint32_t tb = baseu + (uint32_t)(ch % 3) * G3_STAGE;
        mma_half(tb, 0u);
        if (ch + 2 < G3_NCH) load_chunk(ch + 2);
        else CP_COMMIT();
        mma_half(tb, 32u);
        __syncthreads();
    }

    // V-reduction epilogue
    const int r_in = lane >> 2, c2 = (lane & 3) * 2;
    if (tid < 128) sV[tid] = 0.f;
    __syncthreads();
    float tb0 = times_t[read_int(kptr)];
    float cA[4], cB[4], tAv[4], tBv[4];
#pragma unroll
    for (int mi = 0; mi < 4; mi++) {
        size_t rowA = growBase + warp_m * 64 + mi * 16 + r_in;
        cA[mi] = g_coeff[rowA];
        cB[mi] = g_coeff[rowA + 8];
        tAv[mi] = tb0 + times_tau[rowA & 255];
        tBv[mi] = tb0 + times_tau[(rowA + 8) & 255];
    }
#pragma unroll
    for (int nj = 0; nj < 4; nj++) {
        int colL = warp_n * 32 + ((nj >> 1) * 16) + (nj & 1) * 8 + c2;
        int col  = nbase + colL;
        float b0 = g_bb1eff[col], b1 = g_bb1eff[col + 1];
        float tr0 = trow[col], tr1 = trow[col + 1];
        float p0 = 0.f, p1 = 0.f;
#pragma unroll
        for (int mi = 0; mi < 4; mi++) {
            float v00 = fast_tanh(fmaf(tAv[mi], tr0, acc[mi][nj][0] + b0));
            float v01 = fast_tanh(fmaf(tAv[mi], tr1, acc[mi][nj][1] + b1));
            float v10 = fast_tanh(fmaf(tBv[mi], tr0, acc[mi][nj][2] + b0));
            float v11 = fast_tanh(fmaf(tBv[mi], tr1, acc[mi][nj][3] + b1));
            p0 += cA[mi] * v00 + cB[mi] * v10;
            p1 += cA[mi] * v01 + cB[mi] * v11;
        }
#pragma unroll
        for (int off = 4; off <= 16; off <<= 1) {
            p0 += __shfl_xor_sync(0xFFFFFFFFu, p0, off);
            p1 += __shfl_xor_sync(0xFFFFFFFFu, p1, off);
        }
        if (lane < 4) {
            atomicAdd(&sV[colL], p0);
            atomicAdd(&sV[colL + 1], p1);
        }
    }
    __syncthreads();
    if (tid < 128)
        g_Vpart[(size_t)blockIdx.y * HB + nbase + tid] = sV[tid];
}

// ---------------------------------------------------------------------------
// v_sum / final_si
// ---------------------------------------------------------------------------
__global__ void v_sum(const float* __restrict__ Wb2) {
    __shared__ float V[256];
    __shared__ float red[256];
    int tid = threadIdx.x;
    int hb = blockIdx.x * 256 + tid;
    float s = 0.f;
    for (int p = 0; p < MTILES; p++) s += g_Vpart[(size_t)p * HB + hb];
    V[tid] = s;
    __syncthreads();
    int g = tid & 63, c4 = tid >> 6;
    float acc = 0.f;
    for (int hh = c4 * 64; hh < c4 * 64 + 64; hh++)
        acc += V[hh] * Wb2[(size_t)(blockIdx.x * 256 + hh) * GOUT + g];
    red[tid] = acc;
    __syncthreads();
    if (tid < 64)
        g_sipart[blockIdx.x * GOUT + tid] =
            red[tid] + red[tid + 64] + red[tid + 128] + red[tid + 192];
}

__global__ void final_si(float* __restrict__ out) {
    int g = threadIdx.x;
    float acc = 0.f;
#pragma unroll
    for (int c = 0; c < 8; c++) acc += g_sipart[c * GOUT + g];
    out[g] = acc;
}

// ---------------------------------------------------------------------------
// Launch. ncu profiles 0-based launch index 3 -> gemm2.
// ---------------------------------------------------------------------------
extern "C" void kernel_launch(void* const* d_in, const int* in_sizes, int n_in,
                              void* d_out, int out_size) {
    const float* X         = (const float*)d_in[0];
    const float* Y         = (const float*)d_in[1];
    const float* R         = (const float*)d_in[2];
    const float* stoich    = (const float*)d_in[3];
    const float* times_t   = (const float*)d_in[4];
    const float* times_tau = (const float*)d_in[5];
    const float* Wx1       = (const float*)d_in[6];
    const float* bx1       = (const float*)d_in[7];
    const float* Wx2       = (const float*)d_in[8];
    const float* bx2       = (const float*)d_in[9];
    const float* Wih       = (const float*)d_in[10];
    const float* Whh       = (const float*)d_in[11];
    const float* bh        = (const float*)d_in[12];
    const float* Wb1       = (const float*)d_in[13];
    const float* bb1       = (const float*)d_in[14];
    const float* Wb2       = (const float*)d_in[15];
    const int*   kptr      = (const int*)d_in[17];
    const int*   kpptr     = (const int*)d_in[18];
    const int*   qptr      = (const int*)d_in[19];
    const int*   qpptr     = (const int*)d_in[20];
    float* out = (float*)d_out;

    cudaFuncSetAttribute(gemm2_kernel,
                         cudaFuncAttributeMaxDynamicSharedMemorySize, G2_SMEM);
    cudaFuncSetAttribute(gemm3_kernel,
                         cudaFuncAttributeMaxDynamicSharedMemorySize, G3_SMEM);

    prep_w<<<512, dim3(32, 8)>>>(Wx2, 0);                            // 0
    prep_w<<<1024, dim3(32, 8)>>>(Wb1, 1);                           // 1
    pre_h1_kernel<<<MBAR + MR, 256>>>(X, stoich, Wx1, bx1,           // 2
                                      kpptr, qpptr);
    gemm2_kernel<<<dim3(2, 135), 512, G2_SMEM>>>(                    // 3 (ncu)
        bx2, Y, Wih, Whh, bh, kptr, qptr, X, R, stoich, kpptr, qpptr);
    bb1eff_kernel<<<8, 256>>>(Wb1, bb1);                             // 4
    gemm3_kernel<<<dim3(16, MTILES), 256, G3_SMEM>>>(                // 5
        Wb1, times_t, times_tau, kptr);
    v_sum<<<8, 256>>>(Wb2);                                          // 6
    final_si<<<1, 64>>>(out);                                        // 7
}